// round 12
// baseline (speedup 1.0000x reference)
#include <cuda_runtime.h>
#include <cuda_bf16.h>

// CrossNet: B=500000, D=128, L=4.   out = alpha_L * x0 + beta_L
//   d_l = w_l·x0 ; alpha_{l+1} = alpha_l*(1+d_l) + c_l ; c_l = w_l·beta_l
//
// R12: 4 rows per warp (one 8-lane-team group), all checks and 64-bit math
// removed (B=500000 -> 125000 warps -> exactly 15625 blocks). Data regs drop
// to 16, __launch_bounds__(256,6) caps at 42 regs -> 6 blocks/SM (~70% occ)
// vs R11's 4 blocks/42%. Same per-row MIO mix as R11 (1 LDG.128 + 1 STG.128 +
// 3 SHFL + 4 LDS per row); more warps to push DRAM past 76%.

#define CN_L  4
#define CN_D  128

__global__ __launch_bounds__(256, 6) void crossnet_kernel(
    const float4* __restrict__ x,     // inputs  [B,128] as float4 [B,32]
    const float4* __restrict__ w4,    // kernels [L,128] as float4
    const float4* __restrict__ b4,    // biases
    float4*       __restrict__ out)
{
    __shared__ float4 ws[CN_L * 32];  // weights
    __shared__ float4 sbeta[32];      // beta_L
    __shared__ float  sc[CN_L];       // c_l

    const int tid = threadIdx.x;
    if (tid < CN_L * 32) ws[tid] = w4[tid];
    __syncthreads();

    // warp 0: compute beta_L and c_l into smem
    if (tid < 32) {
        const int ln = tid;
        float4 bt = make_float4(0.f, 0.f, 0.f, 0.f);
#pragma unroll
        for (int l = 0; l < CN_L; ++l) {
            const float4 wl = ws[l * 32 + ln];
            float p = wl.x * bt.x;
            p = fmaf(wl.y, bt.y, p);
            p = fmaf(wl.z, bt.z, p);
            p = fmaf(wl.w, bt.w, p);
#pragma unroll
            for (int off = 16; off > 0; off >>= 1)
                p += __shfl_xor_sync(0xffffffffu, p, off);
            if (ln == 0) sc[l] = p;
            const float4 bl = __ldg(&b4[l * 32 + ln]);
            bt.x += bl.x; bt.y += bl.y; bt.z += bl.z; bt.w += bl.w;
        }
        sbeta[ln] = bt;
    }
    __syncthreads();

    const int warp = (blockIdx.x << 3) + (tid >> 5);  // 8 warps/block
    const int lane = tid & 31;
    const int sub  = lane >> 3;     // row within 4-row group (0..3)
    const int li   = lane & 7;      // lane within 8-lane row team

    // this warp's row: 4 consecutive rows, lane's row = warp*4 + sub.
    // float4 index base: row*32 + i*8 + li   (int math: max < 16M)
    const int base = (warp * 4 + sub) * 32 + li;

    // 4 independent LDG.128, front-batched
    float4 xv[4];
#pragma unroll
    for (int i = 0; i < 4; ++i)
        xv[i] = __ldcs(&x[base + i * 8]);

    // partial dots d_l = w_l·x0 over this lane's 16 cols (weights from smem)
    float p[CN_L];
#pragma unroll
    for (int l = 0; l < CN_L; ++l) {
        float q = 0.f;
#pragma unroll
        for (int i = 0; i < 4; ++i) {
            const float4 wv = ws[l * 32 + i * 8 + li];
            q = fmaf(wv.x, xv[i].x, q);
            q = fmaf(wv.y, xv[i].y, q);
            q = fmaf(wv.z, xv[i].z, q);
            q = fmaf(wv.w, xv[i].w, q);
        }
        p[l] = q;
    }
    // 3-level butterfly within 8-lane teams; each SHFL serves 4 rows
#pragma unroll
    for (int off = 1; off < 8; off <<= 1) {
#pragma unroll
        for (int l = 0; l < CN_L; ++l)
            p[l] += __shfl_xor_sync(0xffffffffu, p[l], off);
    }

    // scalar alpha recurrence
    float a = 1.0f;
#pragma unroll
    for (int l = 0; l < CN_L; ++l)
        a = fmaf(a, p[l], a + sc[l]);

    // epilogue: out = a * x0 + beta
#pragma unroll
    for (int i = 0; i < 4; ++i) {
        const float4 bt = sbeta[i * 8 + li];
        float4 o;
        o.x = fmaf(xv[i].x, a, bt.x);
        o.y = fmaf(xv[i].y, a, bt.y);
        o.z = fmaf(xv[i].z, a, bt.z);
        o.w = fmaf(xv[i].w, a, bt.w);
        __stcs(&out[base + i * 8], o);
    }
}

extern "C" void kernel_launch(void* const* d_in, const int* in_sizes, int n_in,
                              void* d_out, int out_size)
{
    const float* x = (const float*)d_in[0];   // inputs  [B,128]
    const float* w = (const float*)d_in[1];   // kernels [L,128,1]
    const float* b = (const float*)d_in[2];   // biases  [L,128,1]
    float* out = (float*)d_out;

    const int B = in_sizes[0] / CN_D;          // 500000
    const int warps = (B + 3) / 4;             // 125000 (exact for B=500000)
    const int grid  = (warps + 7) / 8;         // 15625  (exact)

    crossnet_kernel<<<grid, 256>>>(
        reinterpret_cast<const float4*>(x),
        reinterpret_cast<const float4*>(w),
        reinterpret_cast<const float4*>(b),
        reinterpret_cast<float4*>(out));
}

// round 13
// speedup vs baseline: 1.0665x; 1.0665x over previous
#include <cuda_runtime.h>
#include <cuda_bf16.h>

// CrossNet: B=500000, D=128, L=4.   out = alpha_L * x0 + beta_L
//   d_l = w_l·x0 ; alpha_{l+1} = alpha_l*(1+d_l) + c_l ; c_l = w_l·beta_l
//
// R13: R11's measured-best body (8-lane row teams, 3 SHFL/row, 8 rows/warp
// front-batched -> 8 outstanding LDG.128/lane) with the prologue amputated:
// a one-warp setup kernel computes beta_L/c_l into globals (the 4 serial
// bias LDGs that stalled every block in R12 run once per launch), and the
// main kernel's preamble is one parallel staging pass + one barrier. All
// per-row bounds checks removed (B=500000 = 62500 warps x 8 rows exactly).

#define CN_L  4
#define CN_D  128

__device__ float4 g_beta[32];
__device__ float  g_c[CN_L];

// ---- setup: one warp computes beta_L and c_l ----
__global__ void crossnet_setup(const float4* __restrict__ w4,
                               const float4* __restrict__ b4)
{
    const int ln = threadIdx.x & 31;
    float4 bt = make_float4(0.f, 0.f, 0.f, 0.f);
#pragma unroll
    for (int l = 0; l < CN_L; ++l) {
        const float4 wl = w4[l * 32 + ln];
        float p = wl.x * bt.x;
        p = fmaf(wl.y, bt.y, p);
        p = fmaf(wl.z, bt.z, p);
        p = fmaf(wl.w, bt.w, p);
#pragma unroll
        for (int off = 16; off > 0; off >>= 1)
            p += __shfl_xor_sync(0xffffffffu, p, off);
        if (ln == 0) g_c[l] = p;
        const float4 bl = b4[l * 32 + ln];
        bt.x += bl.x; bt.y += bl.y; bt.z += bl.z; bt.w += bl.w;
    }
    g_beta[ln] = bt;
}

// ---- main kernel ----
__global__ __launch_bounds__(256, 4) void crossnet_kernel(
    const float4* __restrict__ x,     // inputs  [B,128] as float4 [B,32]
    const float4* __restrict__ w4,    // kernels [L,128] as float4
    float4*       __restrict__ out,
    int B)
{
    __shared__ float4 ws[CN_L * 32];  // weights
    __shared__ float4 sbeta[32];      // beta_L
    __shared__ float  sc[CN_L];       // c_l

    const int tid = threadIdx.x;
    // single parallel staging pass, one barrier
    if (tid < 128)       ws[tid]          = w4[tid];
    else if (tid < 160)  sbeta[tid - 128] = g_beta[tid - 128];
    else if (tid < 164)  sc[tid - 160]    = g_c[tid - 160];
    __syncthreads();

    const int warp = (blockIdx.x << 3) + (tid >> 5);
    if (warp * 8 >= B) return;        // only tail warps of the last block

    const int lane = tid & 31;
    const int sub  = lane >> 3;       // row within 4-row group (0..3)
    const int li   = lane & 7;        // lane within 8-lane row team

    // rows: rA = warp*8 + sub, rB = rA + 4. 32-bit float4 indices (< 16M).
    const int baseA = (warp * 8 + sub) * 32 + li;
    const int baseB = baseA + 4 * 32;

    // 8 independent LDG.128 per lane, all front-batched
    float4 xa[4], xb[4];
#pragma unroll
    for (int i = 0; i < 4; ++i) xa[i] = __ldcs(&x[baseA + i * 8]);
#pragma unroll
    for (int i = 0; i < 4; ++i) xb[i] = __ldcs(&x[baseB + i * 8]);

    // partial dots d_l = w_l·x0 over this lane's 16 cols (weights from smem)
    float pa[CN_L], pb[CN_L];
#pragma unroll
    for (int l = 0; l < CN_L; ++l) {
        float qa = 0.f, qb = 0.f;
#pragma unroll
        for (int i = 0; i < 4; ++i) {
            const float4 wv = ws[l * 32 + i * 8 + li];
            qa = fmaf(wv.x, xa[i].x, qa);  qb = fmaf(wv.x, xb[i].x, qb);
            qa = fmaf(wv.y, xa[i].y, qa);  qb = fmaf(wv.y, xb[i].y, qb);
            qa = fmaf(wv.z, xa[i].z, qa);  qb = fmaf(wv.z, xb[i].z, qb);
            qa = fmaf(wv.w, xa[i].w, qa);  qb = fmaf(wv.w, xb[i].w, qb);
        }
        pa[l] = qa; pb[l] = qb;
    }
    // 3-level butterfly within 8-lane teams; each SHFL serves 4 rows
#pragma unroll
    for (int off = 1; off < 8; off <<= 1) {
#pragma unroll
        for (int l = 0; l < CN_L; ++l) {
            pa[l] += __shfl_xor_sync(0xffffffffu, pa[l], off);
            pb[l] += __shfl_xor_sync(0xffffffffu, pb[l], off);
        }
    }

    // scalar alpha recurrences
    float aA = 1.0f, aB = 1.0f;
#pragma unroll
    for (int l = 0; l < CN_L; ++l) {
        const float cl = sc[l];
        aA = fmaf(aA, pa[l], aA + cl);
        aB = fmaf(aB, pb[l], aB + cl);
    }

    // epilogue: out = a * x0 + beta
#pragma unroll
    for (int i = 0; i < 4; ++i) {
        const float4 bt = sbeta[i * 8 + li];
        float4 o;
        o.x = fmaf(xa[i].x, aA, bt.x);
        o.y = fmaf(xa[i].y, aA, bt.y);
        o.z = fmaf(xa[i].z, aA, bt.z);
        o.w = fmaf(xa[i].w, aA, bt.w);
        __stcs(&out[baseA + i * 8], o);
        o.x = fmaf(xb[i].x, aB, bt.x);
        o.y = fmaf(xb[i].y, aB, bt.y);
        o.z = fmaf(xb[i].z, aB, bt.z);
        o.w = fmaf(xb[i].w, aB, bt.w);
        __stcs(&out[baseB + i * 8], o);
    }
}

extern "C" void kernel_launch(void* const* d_in, const int* in_sizes, int n_in,
                              void* d_out, int out_size)
{
    const float* x = (const float*)d_in[0];   // inputs  [B,128]
    const float* w = (const float*)d_in[1];   // kernels [L,128,1]
    const float* b = (const float*)d_in[2];   // biases  [L,128,1]
    float* out = (float*)d_out;

    const int B = in_sizes[0] / CN_D;                       // 500000

    crossnet_setup<<<1, 32>>>(
        reinterpret_cast<const float4*>(w),
        reinterpret_cast<const float4*>(b));

    const int warps = (B + 7) / 8;            // 62500
    const int grid  = (warps + 7) / 8;        // 7813

    crossnet_kernel<<<grid, 256>>>(
        reinterpret_cast<const float4*>(x),
        reinterpret_cast<const float4*>(w),
        reinterpret_cast<float4*>(out), B);
}